// round 5
// baseline (speedup 1.0000x reference)
#include <cuda_runtime.h>

// ---------------------------------------------------------------------------
// LinearAttention (Taylor 2nd-order feature map), b=1, l=1024, dm=1024,
// 16 heads, feature_dim=16, head_dim=64.  D = 1+16+256 = 273 features.
//
// Pipeline:
//   K1: qkv = hidden @ [Wq;Wk;Wv]^T           (fp32 f32x2 GEMM, fused)
//   K2: per (head, chunk): KV_c = phi(k)^T V, Kz_c = sum phi(k)
//   K3: per (head, chunk): prefix state + intra scores (1+s+s^2/2) + output y
//   K4: out = y @ Wo^T                        (fp32 f32x2 GEMM)
// ---------------------------------------------------------------------------

#define LSEQ   1024
#define DMODEL 1024
#define NH     16
#define FDIM   16
#define HDIM   64
#define CHUNK  128
#define NCHUNK 8
#define DFEAT  273
#define DPAD   276
#define PHI_C1 0.5f                      // 1/d^(1/4), d=16
#define PHI_C2 0.17677669529663687f      // 1/(sqrt(2)*sqrt(d))
#define EPSV   1e-12f

// Scratch (static device globals; no allocation allowed)
__device__ __align__(16) float g_qkv[LSEQ * 1536];          // [l][q(256)|k(256)|v(1024)]
__device__ __align__(16) float g_kv[NH * NCHUNK * DPAD * HDIM];
__device__ __align__(16) float g_kz[NH * NCHUNK * DPAD];
__device__ __align__(16) float g_y[LSEQ * DMODEL];

// ---------------- packed f32x2 helpers --------------------------------------
__device__ __forceinline__ unsigned long long pk2(float lo, float hi) {
    unsigned long long r;
    asm("mov.b64 %0, {%1, %2};" : "=l"(r)
        : "r"(__float_as_uint(lo)), "r"(__float_as_uint(hi)));
    return r;
}
__device__ __forceinline__ void ffma2(unsigned long long& d,
                                      unsigned long long a,
                                      unsigned long long b) {
    asm("fma.rn.f32x2 %0, %1, %2, %0;" : "+l"(d) : "l"(a), "l"(b));
}

// ---------------- 64x128 NT GEMM tile (K=1024), f32x2 accumulators ----------
// C[m][n] = sum_k A[m*1024+k] * B[n*1024+k]
__device__ __forceinline__ void gemm_tile_64x128(const float* __restrict__ A,
                                                 const float* __restrict__ B,
                                                 float* __restrict__ C,
                                                 int ldc) {
    __shared__ __align__(16) float As[2][16][64];
    __shared__ __align__(16) float Bs[2][16][128];

    const int tid = threadIdx.x;
    const int ty = tid >> 4, tx = tid & 15;
    const int r0 = ty * 4, c0 = tx * 8;

    const int arow = tid >> 2, ak = (tid & 3) * 4;   // A: 1 float4 / thread
    const int brow = tid >> 1, bk = (tid & 1) * 8;   // B: 2 float4 / thread

    const float* Ap = A + arow * 1024 + ak;
    const float* Bp = B + brow * 1024 + bk;

    unsigned long long acc[4][4];
#pragma unroll
    for (int i = 0; i < 4; i++)
#pragma unroll
        for (int j = 0; j < 4; j++) acc[i][j] = 0ULL;

    float4 ra, rb0, rb1;
    ra  = *(const float4*)Ap;
    rb0 = *(const float4*)Bp;
    rb1 = *(const float4*)(Bp + 4);

    auto do_sts = [&](int buf) {
        As[buf][ak + 0][arow] = ra.x;  As[buf][ak + 1][arow] = ra.y;
        As[buf][ak + 2][arow] = ra.z;  As[buf][ak + 3][arow] = ra.w;
        Bs[buf][bk + 0][brow] = rb0.x; Bs[buf][bk + 1][brow] = rb0.y;
        Bs[buf][bk + 2][brow] = rb0.z; Bs[buf][bk + 3][brow] = rb0.w;
        Bs[buf][bk + 4][brow] = rb1.x; Bs[buf][bk + 5][brow] = rb1.y;
        Bs[buf][bk + 6][brow] = rb1.z; Bs[buf][bk + 7][brow] = rb1.w;
    };

    do_sts(0);
    __syncthreads();

    for (int kt = 0; kt < 64; ++kt) {
        const int cur = kt & 1;
        if (kt < 63) {
            const float* Ap2 = Ap + (kt + 1) * 16;
            const float* Bp2 = Bp + (kt + 1) * 16;
            ra  = *(const float4*)Ap2;
            rb0 = *(const float4*)Bp2;
            rb1 = *(const float4*)(Bp2 + 4);
        }
#pragma unroll
        for (int k = 0; k < 16; k++) {
            float4 a  = *(const float4*)&As[cur][k][r0];
            float4 b0 = *(const float4*)&Bs[cur][k][c0];
            float4 b1 = *(const float4*)&Bs[cur][k][c0 + 4];
            unsigned long long bp0 = pk2(b0.x, b0.y), bp1 = pk2(b0.z, b0.w);
            unsigned long long bp2 = pk2(b1.x, b1.y), bp3 = pk2(b1.z, b1.w);
            float av[4] = {a.x, a.y, a.z, a.w};
#pragma unroll
            for (int i = 0; i < 4; i++) {
                unsigned long long ap = pk2(av[i], av[i]);
                ffma2(acc[i][0], ap, bp0);
                ffma2(acc[i][1], ap, bp1);
                ffma2(acc[i][2], ap, bp2);
                ffma2(acc[i][3], ap, bp3);
            }
        }
        if (kt < 63) do_sts((kt + 1) & 1);
        __syncthreads();
    }

#pragma unroll
    for (int i = 0; i < 4; i++) {
        union { unsigned long long u[2]; float4 v; } lo, hi;
        lo.u[0] = acc[i][0]; lo.u[1] = acc[i][1];
        hi.u[0] = acc[i][2]; hi.u[1] = acc[i][3];
        float* cp = C + (r0 + i) * ldc + c0;
        *(float4*)cp       = lo.v;
        *(float4*)(cp + 4) = hi.v;
    }
}

// ---------------- K1: fused QKV projection ----------------------------------
__global__ __launch_bounds__(256) void gemm_qkv_kernel(
    const float* __restrict__ hs, const float* __restrict__ Wq,
    const float* __restrict__ Wk, const float* __restrict__ Wv) {
    const int n0 = blockIdx.x * 128;    // 0..1408
    const int m0 = blockIdx.y * 64;     // 0..960
    const float* B;
    if (n0 < 256)      B = Wq + n0 * 1024;
    else if (n0 < 512) B = Wk + (n0 - 256) * 1024;
    else               B = Wv + (n0 - 512) * 1024;
    gemm_tile_64x128(hs + m0 * 1024, B, g_qkv + m0 * 1536 + n0, 1536);
}

// ---------------- K4: output projection -------------------------------------
__global__ __launch_bounds__(256) void gemm_out_kernel(
    const float* __restrict__ Wo, float* __restrict__ out) {
    const int n0 = blockIdx.x * 128;
    const int m0 = blockIdx.y * 64;
    gemm_tile_64x128(g_y + m0 * 1024, Wo + n0 * 1024, out + m0 * 1024 + n0, 1024);
}

// ---------------- K2: per-chunk KV / Kz sums --------------------------------
// smem: phik[128][276] | vbuf[128][64] | kbuf[128][16]
#define K2_SMEM ((128 * DPAD + 128 * 64 + 128 * 16) * 4)

__global__ __launch_bounds__(256) void chunk_kv_kernel() {
    extern __shared__ __align__(16) float sm2[];
    float* phik = sm2;                        // 128*276
    float* vbuf = phik + 128 * DPAD;          // 128*64
    float* kbuf = vbuf + 128 * 64;            // 128*16

    const int c = blockIdx.x, h = blockIdx.y;
    const int tid = threadIdx.x;
    const int rowbase = c * CHUNK;

    for (int i = tid; i < 512; i += 256) {
        int t = i >> 2, q4 = (i & 3) * 4;
        *(float4*)&kbuf[t * 16 + q4] =
            *(const float4*)&g_qkv[(rowbase + t) * 1536 + 256 + h * 16 + q4];
    }
    for (int i = tid; i < 2048; i += 256) {
        int t = i >> 4, q4 = (i & 15) * 4;
        *(float4*)&vbuf[t * 64 + q4] =
            *(const float4*)&g_qkv[(rowbase + t) * 1536 + 512 + h * 64 + q4];
    }
    __syncthreads();

    // Build phi(k): [1, k/2, k_i k_j / (4*sqrt2)] (+ zero pad D=273..275)
    for (int idx = tid; idx < 128 * DPAD; idx += 256) {
        int t = idx / DPAD;
        int D = idx - t * DPAD;
        float val;
        if (D == 0)        val = 1.0f;
        else if (D <= 16)  val = kbuf[t * 16 + (D - 1)] * PHI_C1;
        else if (D < DFEAT) {
            int e = D - 17;
            val = kbuf[t * 16 + (e >> 4)] * kbuf[t * 16 + (e & 15)] * PHI_C2;
        } else val = 0.0f;
        phik[idx] = val;
    }
    __syncthreads();

    // KV[D][j] = sum_t phik[t][D] * v[t][j]   (69 D-tiles x 32 j-tiles)
    float* KVout = g_kv + (h * NCHUNK + c) * DPAD * HDIM;
    for (int tile = tid; tile < 69 * 32; tile += 256) {
        const int d0 = (tile >> 5) * 4;
        const int j0 = (tile & 31) * 2;
        float a00 = 0, a01 = 0, a10 = 0, a11 = 0;
        float a20 = 0, a21 = 0, a30 = 0, a31 = 0;
#pragma unroll 4
        for (int t = 0; t < 128; t++) {
            float4 p = *(const float4*)&phik[t * DPAD + d0];
            float2 v2 = *(const float2*)&vbuf[t * 64 + j0];
            a00 += p.x * v2.x; a01 += p.x * v2.y;
            a10 += p.y * v2.x; a11 += p.y * v2.y;
            a20 += p.z * v2.x; a21 += p.z * v2.y;
            a30 += p.w * v2.x; a31 += p.w * v2.y;
        }
        *(float2*)&KVout[(d0 + 0) * 64 + j0] = make_float2(a00, a01);
        *(float2*)&KVout[(d0 + 1) * 64 + j0] = make_float2(a10, a11);
        *(float2*)&KVout[(d0 + 2) * 64 + j0] = make_float2(a20, a21);
        *(float2*)&KVout[(d0 + 3) * 64 + j0] = make_float2(a30, a31);
    }

    // Kz[D] = sum_t phik[t][D]
    float* Kzout = g_kz + (h * NCHUNK + c) * DPAD;
    for (int D = tid; D < DFEAT; D += 256) {
        float s = 0;
#pragma unroll 4
        for (int t = 0; t < 128; t++) s += phik[t * DPAD + D];
        Kzout[D] = s;
    }
}

// ---------------- K3: attention core ----------------------------------------
// smem: S[273][64] | z[276] | score[128][129] | q[128][16] | k[128][16] | v[128][64]
#define K3_SF  (DFEAT * 64)
#define K3_SMEM ((K3_SF + DPAD + 128 * 129 + 2048 + 2048 + 8192) * 4)

__global__ __launch_bounds__(256) void attn_kernel() {
    extern __shared__ __align__(16) float sm3[];
    float* S     = sm3;                    // 17472
    float* zbuf  = S + K3_SF;              // 276
    float* score = zbuf + DPAD;            // 128*129
    float* qbuf  = score + 128 * 129;      // 2048
    float* kbuf  = qbuf + 2048;            // 2048
    float* vbuf  = kbuf + 2048;            // 8192

    const int c = blockIdx.x, h = blockIdx.y;
    const int tid = threadIdx.x;
    const int rowbase = c * CHUNK;

    // ---- load q,k,v chunk
    for (int i = tid; i < 512; i += 256) {
        int t = i >> 2, q4 = (i & 3) * 4;
        const float* base = &g_qkv[(rowbase + t) * 1536];
        *(float4*)&qbuf[t * 16 + q4] = *(const float4*)&base[h * 16 + q4];
        *(float4*)&kbuf[t * 16 + q4] = *(const float4*)&base[256 + h * 16 + q4];
    }
    for (int i = tid; i < 2048; i += 256) {
        int t = i >> 4, q4 = (i & 15) * 4;
        *(float4*)&vbuf[t * 64 + q4] =
            *(const float4*)&g_qkv[(rowbase + t) * 1536 + 512 + h * 64 + q4];
    }

    // ---- exclusive chunk-prefix state S, z
    {
        const float* base = g_kv + (h * NCHUNK) * DPAD * HDIM;
        for (int i = tid; i < K3_SF / 4; i += 256) {
            float4 a = make_float4(0.f, 0.f, 0.f, 0.f);
            for (int cc = 0; cc < c; cc++) {
                float4 kv = *(const float4*)(base + cc * DPAD * HDIM + i * 4);
                a.x += kv.x; a.y += kv.y; a.z += kv.z; a.w += kv.w;
            }
            *(float4*)&S[i * 4] = a;
        }
        for (int D = tid; D < DFEAT; D += 256) {
            float s = 0;
            for (int cc = 0; cc < c; cc++) s += g_kz[(h * NCHUNK + cc) * DPAD + D];
            zbuf[D] = s;
        }
    }
    __syncthreads();

    const int t  = tid >> 1;
    const int jh = tid & 1;
    const int j0 = jh * 32;

    // q_t into registers
    float qv[16];
#pragma unroll
    for (int i = 0; i < 16; i += 4) {
        float4 f = *(const float4*)&qbuf[t * 16 + i];
        qv[i] = f.x; qv[i + 1] = f.y; qv[i + 2] = f.z; qv[i + 3] = f.w;
    }

    // ---- intra-chunk scores: phi(q).phi(k) = 1 + s + s^2/2, s = q.k/4
    {
        const int sbase = jh * 64;
        for (int s2 = 0; s2 < 64; s2++) {
            const int s = sbase + s2;
            float dot = 0;
#pragma unroll
            for (int i = 0; i < 16; i += 4) {
                float4 kk = *(const float4*)&kbuf[s * 16 + i];
                dot += qv[i] * kk.x + qv[i + 1] * kk.y +
                       qv[i + 2] * kk.z + qv[i + 3] * kk.w;
            }
            float sd = dot * 0.25f;
            float sc = 1.0f + sd + 0.5f * sd * sd;
            score[t * 129 + s] = (s <= t) ? sc : 0.0f;
        }
    }
    __syncthreads();

    float acc[32];
#pragma unroll
    for (int i = 0; i < 32; i++) acc[i] = 0.f;
    float den = 0.f;

    // ---- intra: num += score @ V, den += sum score   (warp-uniform bound)
    const int send = (t & ~15) + 16;
    for (int s = 0; s < send; s++) {
        const float sc = score[t * 129 + s];
        den += sc;
        const float* vp = &vbuf[s * 64 + j0];
#pragma unroll
        for (int g = 0; g < 8; g++) {
            float4 vv = *(const float4*)&vp[g * 4];
            acc[g * 4 + 0] += sc * vv.x; acc[g * 4 + 1] += sc * vv.y;
            acc[g * 4 + 2] += sc * vv.z; acc[g * 4 + 3] += sc * vv.w;
        }
    }

    // ---- inter: num += phi(q_t) . S,  den += phi(q_t) . z
    {   // D = 0 (phi = 1)
        const float* Srow = S + j0;
#pragma unroll
        for (int g = 0; g < 8; g++) {
            float4 sv = *(const float4*)&Srow[g * 4];
            acc[g * 4 + 0] += sv.x; acc[g * 4 + 1] += sv.y;
            acc[g * 4 + 2] += sv.z; acc[g * 4 + 3] += sv.w;
        }
        den += zbuf[0];
    }
#pragma unroll 4
    for (int i = 0; i < 16; i++) {   // linear terms
        const float phi = qv[i] * PHI_C1;
        const float* Srow = S + (1 + i) * 64 + j0;
#pragma unroll
        for (int g = 0; g < 8; g++) {
            float4 sv = *(const float4*)&Srow[g * 4];
            acc[g * 4 + 0] += phi * sv.x; acc[g * 4 + 1] += phi * sv.y;
            acc[g * 4 + 2] += phi * sv.z; acc[g * 4 + 3] += phi * sv.w;
        }
        den += phi * zbuf[1 + i];
    }
    for (int i = 0; i < 16; i++) {   // quadratic terms
        const float qi = qv[i] * PHI_C2;
#pragma unroll 4
        for (int jj = 0; jj < 16; jj++) {
            const float phi = qi * qv[jj];
            const int D = 17 + i * 16 + jj;
            const float* Srow = S + D * 64 + j0;
#pragma unroll
            for (int g = 0; g < 8; g++) {
                float4 sv = *(const float4*)&Srow[g * 4];
                acc[g * 4 + 0] += phi * sv.x; acc[g * 4 + 1] += phi * sv.y;
                acc[g * 4 + 2] += phi * sv.z; acc[g * 4 + 3] += phi * sv.w;
            }
            den += phi * zbuf[D];
        }
    }

    // ---- y = num / (den + eps) -> g_y[l][h*64 + j]
    const float rden = 1.0f / (den + EPSV);
    float* yp = g_y + (rowbase + t) * DMODEL + h * HDIM + j0;
#pragma unroll
    for (int g = 0; g < 8; g++) {
        float4 o = make_float4(acc[g * 4 + 0] * rden, acc[g * 4 + 1] * rden,
                               acc[g * 4 + 2] * rden, acc[g * 4 + 3] * rden);
        *(float4*)&yp[g * 4] = o;
    }
}

// ---------------------------------------------------------------------------
extern "C" void kernel_launch(void* const* d_in, const int* in_sizes, int n_in,
                              void* d_out, int out_size) {
    (void)in_sizes; (void)n_in; (void)out_size;
    const float* hs = (const float*)d_in[0];
    const float* Wq = (const float*)d_in[1];
    const float* Wk = (const float*)d_in[2];
    const float* Wv = (const float*)d_in[3];
    const float* Wo = (const float*)d_in[4];
    float* out = (float*)d_out;

    cudaFuncSetAttribute(chunk_kv_kernel,
                         cudaFuncAttributeMaxDynamicSharedMemorySize, K2_SMEM);
    cudaFuncSetAttribute(attn_kernel,
                         cudaFuncAttributeMaxDynamicSharedMemorySize, K3_SMEM);

    gemm_qkv_kernel<<<dim3(12, 16), 256>>>(hs, Wq, Wk, Wv);
    chunk_kv_kernel<<<dim3(NCHUNK, NH), 256, K2_SMEM>>>();
    attn_kernel<<<dim3(NCHUNK, NH), 256, K3_SMEM>>>();
    gemm_out_kernel<<<dim3(8, 16), 256>>>(Wo, out);
}

// round 7
// speedup vs baseline: 1.6591x; 1.6591x over previous
#include <cuda_runtime.h>
#include <cuda_bf16.h>
#include <cstdint>

// ---------------------------------------------------------------------------
// LinearAttention (Taylor 2nd-order feature map), b=1, l=1024, dm=1024,
// 16 heads, feature_dim=16, head_dim=64.  D = 1+16+256 = 273 features.
//
// Pipeline:
//   S1: split hs -> bf16 [hi|hi|lo]  (K=3072), split [Wq;Wk;Wv] -> [hi|lo|hi]
//   G1: qkv = hs2 @ W1^T via mma.sync bf16 (split-bf16 ~ fp32 precision)
//   K2: per (head, chunk): KV_c = phi(k)^T V, Kz_c = sum phi(k)
//   K3: per (head, chunk): prefix state + intra scores (1+s+s^2/2) + output y
//   S2: split y
//   G2: out = y2 @ Wo2^T via mma.sync
// ---------------------------------------------------------------------------

#define LSEQ   1024
#define DMODEL 1024
#define NH     16
#define FDIM   16
#define HDIM   64
#define CHUNK  128
#define NCHUNK 8
#define DFEAT  273
#define DPAD   276
#define PHI_C1 0.5f                      // 1/d^(1/4), d=16
#define PHI_C2 0.17677669529663687f      // 1/(sqrt(2)*sqrt(d))
#define EPSV   1e-12f
#define KSPLIT 3072                      // 3 x 1024 split-bf16 K
#define NSTAGE 48                        // 3072 / 64

// Scratch (static device globals; no allocation allowed)
__device__ __align__(16) float g_qkv[LSEQ * 1536];          // [l][q|k|v]
__device__ __align__(16) float g_kv[NH * NCHUNK * DPAD * HDIM];
__device__ __align__(16) float g_kz[NH * NCHUNK * DPAD];
__device__ __align__(16) float g_y[LSEQ * DMODEL];
__device__ __align__(16) __nv_bfloat16 g_hs2[LSEQ * KSPLIT];
__device__ __align__(16) __nv_bfloat16 g_w1 [1536 * KSPLIT];
__device__ __align__(16) __nv_bfloat16 g_y2 [LSEQ * KSPLIT];
__device__ __align__(16) __nv_bfloat16 g_wo2[DMODEL * KSPLIT];

// ---------------- packed f32x2 helpers --------------------------------------
__device__ __forceinline__ unsigned long long pk2(float lo, float hi) {
    unsigned long long r;
    asm("mov.b64 %0, {%1, %2};" : "=l"(r)
        : "r"(__float_as_uint(lo)), "r"(__float_as_uint(hi)));
    return r;
}
__device__ __forceinline__ void ffma2(unsigned long long& d,
                                      unsigned long long a,
                                      unsigned long long b) {
    asm("fma.rn.f32x2 %0, %1, %2, %0;" : "+l"(d) : "l"(a), "l"(b));
}
__device__ __forceinline__ void upk2(unsigned long long v, float& lo, float& hi) {
    uint32_t a, b;
    asm("mov.b64 {%0, %1}, %2;" : "=r"(a), "=r"(b) : "l"(v));
    lo = __uint_as_float(a); hi = __uint_as_float(b);
}

// ---------------- PTX helpers (cp.async / ldmatrix / mma) -------------------
__device__ __forceinline__ uint32_t smem_u32(const void* p) {
    uint32_t a;
    asm("{ .reg .u64 t; cvta.to.shared.u64 t, %1; cvt.u32.u64 %0, t; }"
        : "=r"(a) : "l"(p));
    return a;
}
__device__ __forceinline__ void cp16(uint32_t saddr, const void* g) {
    asm volatile("cp.async.cg.shared.global [%0], [%1], 16;"
                 :: "r"(saddr), "l"(g) : "memory");
}
__device__ __forceinline__ void ldsm_x4(uint32_t& r0, uint32_t& r1,
                                        uint32_t& r2, uint32_t& r3,
                                        uint32_t addr) {
    asm volatile("ldmatrix.sync.aligned.m8n8.x4.shared.b16 {%0,%1,%2,%3}, [%4];"
                 : "=r"(r0), "=r"(r1), "=r"(r2), "=r"(r3) : "r"(addr));
}
__device__ __forceinline__ void mma16816(float* c, const uint32_t* a,
                                         const uint32_t* b) {
    asm volatile("mma.sync.aligned.m16n8k16.row.col.f32.bf16.bf16.f32 "
                 "{%0,%1,%2,%3}, {%4,%5,%6,%7}, {%8,%9}, {%0,%1,%2,%3};"
                 : "+f"(c[0]), "+f"(c[1]), "+f"(c[2]), "+f"(c[3])
                 : "r"(a[0]), "r"(a[1]), "r"(a[2]), "r"(a[3]),
                   "r"(b[0]), "r"(b[1]));
}

// ---------------- split kernels (fp32 -> split-bf16, K-concatenated) --------
__device__ __forceinline__ void split4(float4 x, __nv_bfloat162& h01,
                                       __nv_bfloat162& h23, __nv_bfloat162& l01,
                                       __nv_bfloat162& l23) {
    h01 = __floats2bfloat162_rn(x.x, x.y);
    h23 = __floats2bfloat162_rn(x.z, x.w);
    l01 = __floats2bfloat162_rn(x.x - __bfloat162float(h01.x),
                                x.y - __bfloat162float(h01.y));
    l23 = __floats2bfloat162_rn(x.z - __bfloat162float(h23.x),
                                x.w - __bfloat162float(h23.y));
}

// A layout: [hi | hi | lo]
__global__ __launch_bounds__(256) void split_a_kernel(
    const float* __restrict__ src, __nv_bfloat16* __restrict__ dst) {
    int r = blockIdx.x, c = threadIdx.x * 4;
    float4 x = *(const float4*)&src[(size_t)r * 1024 + c];
    __nv_bfloat162 h01, h23, l01, l23;
    split4(x, h01, h23, l01, l23);
    __nv_bfloat162* d0 = (__nv_bfloat162*)&dst[(size_t)r * KSPLIT + c];
    __nv_bfloat162* d1 = (__nv_bfloat162*)&dst[(size_t)r * KSPLIT + 1024 + c];
    __nv_bfloat162* d2 = (__nv_bfloat162*)&dst[(size_t)r * KSPLIT + 2048 + c];
    d0[0] = h01; d0[1] = h23;
    d1[0] = h01; d1[1] = h23;
    d2[0] = l01; d2[1] = l23;
}

// B layout: [hi | lo | hi]
__global__ __launch_bounds__(256) void split_b_kernel(
    const float* __restrict__ src, __nv_bfloat16* __restrict__ dst) {
    int r = blockIdx.x, c = threadIdx.x * 4;
    float4 x = *(const float4*)&src[(size_t)r * 1024 + c];
    __nv_bfloat162 h01, h23, l01, l23;
    split4(x, h01, h23, l01, l23);
    __nv_bfloat162* d0 = (__nv_bfloat162*)&dst[(size_t)r * KSPLIT + c];
    __nv_bfloat162* d1 = (__nv_bfloat162*)&dst[(size_t)r * KSPLIT + 1024 + c];
    __nv_bfloat162* d2 = (__nv_bfloat162*)&dst[(size_t)r * KSPLIT + 2048 + c];
    d0[0] = h01; d0[1] = h23;
    d1[0] = l01; d1[1] = l23;
    d2[0] = h01; d2[1] = h23;
}

__global__ __launch_bounds__(256) void split_w1_kernel(
    const float* __restrict__ Wq, const float* __restrict__ Wk,
    const float* __restrict__ Wv, __nv_bfloat16* __restrict__ dst) {
    int r = blockIdx.x, c = threadIdx.x * 4;
    const float* src; int rr;
    if (r < 256)      { src = Wq; rr = r; }
    else if (r < 512) { src = Wk; rr = r - 256; }
    else              { src = Wv; rr = r - 512; }
    float4 x = *(const float4*)&src[(size_t)rr * 1024 + c];
    __nv_bfloat162 h01, h23, l01, l23;
    split4(x, h01, h23, l01, l23);
    __nv_bfloat162* d0 = (__nv_bfloat162*)&dst[(size_t)r * KSPLIT + c];
    __nv_bfloat162* d1 = (__nv_bfloat162*)&dst[(size_t)r * KSPLIT + 1024 + c];
    __nv_bfloat162* d2 = (__nv_bfloat162*)&dst[(size_t)r * KSPLIT + 2048 + c];
    d0[0] = h01; d0[1] = h23;
    d1[0] = l01; d1[1] = l23;
    d2[0] = h01; d2[1] = h23;
}

// ---------------- mma.sync bf16 NT GEMM: C 128x128 tiles, K=3072 ------------
// smem rows padded to 144B so ldmatrix 8-row groups hit distinct 16B banks.
#define ROWB 144
#define STAGE_BYTES (2 * 128 * ROWB)        // A tile + B tile = 36864
#define MMA_SMEM (2 * STAGE_BYTES)          // double buffered = 73728

__global__ __launch_bounds__(256) void mma_gemm_kernel(
    const __nv_bfloat16* __restrict__ A, const __nv_bfloat16* __restrict__ B,
    float* __restrict__ C, int ldc) {
    extern __shared__ __align__(128) char sm[];
    const uint32_t sbase = smem_u32(sm);
    const int tid = threadIdx.x, lid = tid & 31, wid = tid >> 5;
    const int m0 = blockIdx.y * 128, n0 = blockIdx.x * 128;
    const int wm = wid & 1, wn = wid >> 1;   // 2 x 4 warp grid

    auto load_stage = [&](int s, int buf) {
        const uint32_t ab = sbase + buf * STAGE_BYTES;
        const uint32_t bb = ab + 128 * ROWB;
        const __nv_bfloat16* Ag = A + (size_t)m0 * KSPLIT + s * 64;
        const __nv_bfloat16* Bg = B + (size_t)n0 * KSPLIT + s * 64;
#pragma unroll
        for (int i = 0; i < 4; i++) {
            int idx = tid + i * 256;
            int row = idx >> 3, ch = idx & 7;
            cp16(ab + row * ROWB + ch * 16, Ag + (size_t)row * KSPLIT + ch * 8);
            cp16(bb + row * ROWB + ch * 16, Bg + (size_t)row * KSPLIT + ch * 8);
        }
        asm volatile("cp.async.commit_group;" ::: "memory");
    };

    float acc[4][4][4];
#pragma unroll
    for (int mt = 0; mt < 4; mt++)
#pragma unroll
        for (int nt = 0; nt < 4; nt++)
#pragma unroll
            for (int i = 0; i < 4; i++) acc[mt][nt][i] = 0.f;

    load_stage(0, 0);
    load_stage(1, 1);

    for (int s = 0; s < NSTAGE; s++) {
        const int buf = s & 1;
        if (s == NSTAGE - 1)
            asm volatile("cp.async.wait_group 0;" ::: "memory");
        else
            asm volatile("cp.async.wait_group 1;" ::: "memory");
        __syncthreads();

        const uint32_t abase = sbase + buf * STAGE_BYTES +
                               (wm * 64 + (lid & 15)) * ROWB + (lid >> 4) * 16;
        const uint32_t bbase = sbase + buf * STAGE_BYTES + 128 * ROWB +
                               (wn * 32 + (lid & 15)) * ROWB + (lid >> 4) * 16;
#pragma unroll
        for (int k = 0; k < 4; k++) {        // 4 x k16 per stage
            uint32_t af[4][4], bf[4][2];
#pragma unroll
            for (int mt = 0; mt < 4; mt++)
                ldsm_x4(af[mt][0], af[mt][1], af[mt][2], af[mt][3],
                        abase + mt * 16 * ROWB + k * 32);
#pragma unroll
            for (int nt2 = 0; nt2 < 2; nt2++) {
                uint32_t r0, r1, r2, r3;
                ldsm_x4(r0, r1, r2, r3, bbase + nt2 * 16 * ROWB + k * 32);
                bf[2 * nt2][0] = r0; bf[2 * nt2][1] = r2;
                bf[2 * nt2 + 1][0] = r1; bf[2 * nt2 + 1][1] = r3;
            }
#pragma unroll
            for (int mt = 0; mt < 4; mt++)
#pragma unroll
                for (int nt = 0; nt < 4; nt++)
                    mma16816(acc[mt][nt], af[mt], bf[nt]);
        }
        __syncthreads();
        if (s + 2 < NSTAGE) load_stage(s + 2, buf);
    }

    // epilogue: direct float2 stores
    const int r = lid >> 2, cq = (lid & 3) * 2;
#pragma unroll
    for (int mt = 0; mt < 4; mt++) {
        const int mrow = m0 + wm * 64 + mt * 16 + r;
#pragma unroll
        for (int nt = 0; nt < 4; nt++) {
            const int col = n0 + wn * 32 + nt * 8 + cq;
            *(float2*)&C[(size_t)mrow * ldc + col] =
                make_float2(acc[mt][nt][0], acc[mt][nt][1]);
            *(float2*)&C[(size_t)(mrow + 8) * ldc + col] =
                make_float2(acc[mt][nt][2], acc[mt][nt][3]);
        }
    }
}

// ---------------- K2: per-chunk KV / Kz sums --------------------------------
#define K2_SMEM ((128 * DPAD + 128 * 64 + 128 * 16) * 4)

__global__ __launch_bounds__(256) void chunk_kv_kernel() {
    extern __shared__ __align__(16) float sm2[];
    float* phik = sm2;
    float* vbuf = phik + 128 * DPAD;
    float* kbuf = vbuf + 128 * 64;

    const int c = blockIdx.x, h = blockIdx.y;
    const int tid = threadIdx.x;
    const int rowbase = c * CHUNK;

    for (int i = tid; i < 512; i += 256) {
        int t = i >> 2, q4 = (i & 3) * 4;
        *(float4*)&kbuf[t * 16 + q4] =
            *(const float4*)&g_qkv[(rowbase + t) * 1536 + 256 + h * 16 + q4];
    }
    for (int i = tid; i < 2048; i += 256) {
        int t = i >> 4, q4 = (i & 15) * 4;
        *(float4*)&vbuf[t * 64 + q4] =
            *(const float4*)&g_qkv[(rowbase + t) * 1536 + 512 + h * 64 + q4];
    }
    __syncthreads();

    for (int idx = tid; idx < 128 * DPAD; idx += 256) {
        int t = idx / DPAD;
        int D = idx - t * DPAD;
        float val;
        if (D == 0)        val = 1.0f;
        else if (D <= 16)  val = kbuf[t * 16 + (D - 1)] * PHI_C1;
        else if (D < DFEAT) {
            int e = D - 17;
            val = kbuf[t * 16 + (e >> 4)] * kbuf[t * 16 + (e & 15)] * PHI_C2;
        } else val = 0.0f;
        phik[idx] = val;
    }
    __syncthreads();

    float* KVout = g_kv + (h * NCHUNK + c) * DPAD * HDIM;
    for (int tile = tid; tile < 69 * 32; tile += 256) {
        const int d0 = (tile >> 5) * 4;
        const int j0 = (tile & 31) * 2;
        float a00 = 0, a01 = 0, a10 = 0, a11 = 0;
        float a20 = 0, a21 = 0, a30 = 0, a31 = 0;
#pragma unroll 4
        for (int t = 0; t < 128; t++) {
            float4 p = *(const float4*)&phik[t * DPAD + d0];
            float2 v2 = *(const float2*)&vbuf[t * 64 + j0];
            a00 += p.x * v2.x; a01 += p.x * v2.y;
            a10 += p.y * v2.x; a11 += p.y * v2.y;
            a20 += p.z * v2.x; a21 += p.z * v2.y;
            a30 += p.w * v2.x; a31 += p.w * v2.y;
        }
        *(float2*)&KVout[(d0 + 0) * 64 + j0] = make_float2(a00, a01);
        *(float2*)&KVout[(d0 + 1) * 64 + j0] = make_float2(a10, a11);
        *(float2*)&KVout[(d0 + 2) * 64 + j0] = make_float2(a20, a21);
        *(float2*)&KVout[(d0 + 3) * 64 + j0] = make_float2(a30, a31);
    }

    float* Kzout = g_kz + (h * NCHUNK + c) * DPAD;
    for (int D = tid; D < DFEAT; D += 256) {
        float s = 0;
#pragma unroll 4
        for (int t = 0; t < 128; t++) s += phik[t * DPAD + D];
        Kzout[D] = s;
    }
}

// ---------------- K3: attention core (f32x2 packed math) --------------------
#define K3_SF  (DFEAT * 64)
#define K3_SMEM ((K3_SF + DPAD + 128 * 129 + 2048 + 2048 + 8192) * 4)

__global__ __launch_bounds__(256) void attn_kernel() {
    extern __shared__ __align__(16) float sm3[];
    float* S     = sm3;
    float* zbuf  = S + K3_SF;
    float* score = zbuf + DPAD;
    float* qbuf  = score + 128 * 129;
    float* kbuf  = qbuf + 2048;
    float* vbuf  = kbuf + 2048;

    const int c = blockIdx.x, h = blockIdx.y;
    const int tid = threadIdx.x;
    const int rowbase = c * CHUNK;

    for (int i = tid; i < 512; i += 256) {
        int t = i >> 2, q4 = (i & 3) * 4;
        const float* base = &g_qkv[(rowbase + t) * 1536];
        *(float4*)&qbuf[t * 16 + q4] = *(const float4*)&base[h * 16 + q4];
        *(float4*)&kbuf[t * 16 + q4] = *(const float4*)&base[256 + h * 16 + q4];
    }
    for (int i = tid; i < 2048; i += 256) {
        int t = i >> 4, q4 = (i & 15) * 4;
        *(float4*)&vbuf[t * 64 + q4] =
            *(const float4*)&g_qkv[(rowbase + t) * 1536 + 512 + h * 64 + q4];
    }

    {   // exclusive chunk-prefix state S, z
        const float* base = g_kv + (h * NCHUNK) * DPAD * HDIM;
        for (int i = tid; i < K3_SF / 4; i += 256) {
            float4 a = make_float4(0.f, 0.f, 0.f, 0.f);
            for (int cc = 0; cc < c; cc++) {
                float4 kv = *(const float4*)(base + cc * DPAD * HDIM + i * 4);
                a.x += kv.x; a.y += kv.y; a.z += kv.z; a.w += kv.w;
            }
            *(float4*)&S[i * 4] = a;
        }
        for (int D = tid; D < DFEAT; D += 256) {
            float s = 0;
            for (int cc = 0; cc < c; cc++) s += g_kz[(h * NCHUNK + cc) * DPAD + D];
            zbuf[D] = s;
        }
    }
    __syncthreads();

    const int t  = tid >> 1;
    const int jh = tid & 1;
    const int j0 = jh * 32;

    float qv[16];
#pragma unroll
    for (int i = 0; i < 16; i += 4) {
        float4 f = *(const float4*)&qbuf[t * 16 + i];
        qv[i] = f.x; qv[i + 1] = f.y; qv[i + 2] = f.z; qv[i + 3] = f.w;
    }
    unsigned long long qp[8];
#pragma unroll
    for (int i = 0; i < 8; i++) qp[i] = pk2(qv[2 * i], qv[2 * i + 1]);

    // intra-chunk scores: phi(q).phi(k) = 1 + s + s^2/2, s = q.k/4
    {
        const int sbase = jh * 64;
        for (int s2 = 0; s2 < 64; s2++) {
            const int s = sbase + s2;
            unsigned long long dacc = 0ULL;
            const unsigned long long* kp = (const unsigned long long*)&kbuf[s * 16];
#pragma unroll
            for (int i = 0; i < 8; i++) ffma2(dacc, qp[i], kp[i]);
            float dlo, dhi; upk2(dacc, dlo, dhi);
            float sd = (dlo + dhi) * 0.25f;
            float sc = fmaf(0.5f * sd, sd, 1.0f + sd);
            score[t * 129 + s] = (s <= t) ? sc : 0.0f;
        }
    }
    __syncthreads();

    unsigned long long accp[16];
#pragma unroll
    for (int i = 0; i < 16; i++) accp[i] = 0ULL;
    float den = 0.f;

    // intra: num += score @ V, den += sum score  (warp-uniform bound)
    const int send = (t & ~15) + 16;
    for (int s = 0; s < send; s++) {
        const float sc = score[t * 129 + s];
        den += sc;
        const unsigned long long scp = pk2(sc, sc);
        const ulonglong2* vp = (const ulonglong2*)&vbuf[s * 64 + j0];
#pragma unroll
        for (int g = 0; g < 8; g++) {
            ulonglong2 vv = vp[g];
            ffma2(accp[2 * g], scp, vv.x);
            ffma2(accp[2 * g + 1], scp, vv.y);
        }
    }

    // inter: num += phi(q_t) . S, den += phi(q_t) . z
    {
        const unsigned long long one2 = pk2(1.0f, 1.0f);
        const ulonglong2* Sp = (const ulonglong2*)&S[j0];
#pragma unroll
        for (int g = 0; g < 8; g++) {
            ulonglong2 sv = Sp[g];
            ffma2(accp[2 * g], one2, sv.x);
            ffma2(accp[2 * g + 1], one2, sv.y);
        }
        den += zbuf[0];
    }
#pragma unroll 4
    for (int i = 0; i < 16; i++) {   // linear terms
        const float phi = qv[i] * PHI_C1;
        const unsigned long long php = pk2(phi, phi);
        const ulonglong2* Sp = (const ulonglong2*)&S[(1 + i) * 64 + j0];
#pragma unroll
        for (int g = 0; g < 8; g++) {
            ulonglong2 sv = Sp[g];
            ffma2(accp[2 * g], php, sv.x);
            ffma2(accp[2 * g + 1], php, sv.y);
        }
        den = fmaf(phi, zbuf[1 + i], den);
    }
    for (int i = 0; i < 16; i++) {   // quadratic terms
        const float qi = qv[i] * PHI_C2;
#pragma unroll 4
        for (int jj = 0; jj < 16; jj++) {
            const float phi = qi * qv[jj];
            const unsigned long long php = pk2(phi, phi);
            const int D = 17 + i * 16 + jj;
            const ulonglong2* Sp = (const ulonglong2*)&S[D * 64 + j0];
#pragma unroll
            for (int g = 0; g < 8; g++) {
                ulonglong2 sv = Sp[g];
                ffma2(accp[2 * g], php, sv.x);
                ffma2(accp[2 * g + 1], php, sv.y);
            }
            den = fmaf(phi, zbuf[D], den);
        }
    }

    // y = num / (den + eps)
    const float rden = 1.0f / (den + EPSV);
    float* yp = g_y + (rowbase + t) * DMODEL + h * HDIM + j0;
#pragma unroll
    for (int g = 0; g < 8; g++) {
        float a0, a1, a2, a3;
        upk2(accp[2 * g], a0, a1);
        upk2(accp[2 * g + 1], a2, a3);
        *(float4*)&yp[g * 4] = make_float4(a0 * rden, a1 * rden, a2 * rden, a3 * rden);
    }
}

// ---------------------------------------------------------------------------
extern "C" void kernel_launch(void* const* d_in, const int* in_sizes, int n_in,
                              void* d_out, int out_size) {
    (void)in_sizes; (void)n_in; (void)out_size;
    const float* hs = (const float*)d_in[0];
    const float* Wq = (const float*)d_in[1];
    const float* Wk = (const float*)d_in[2];
    const float* Wv = (const float*)d_in[3];
    const float* Wo = (const float*)d_in[4];
    float* out = (float*)d_out;

    cudaFuncSetAttribute(mma_gemm_kernel,
                         cudaFuncAttributeMaxDynamicSharedMemorySize, MMA_SMEM);
    cudaFuncSetAttribute(chunk_kv_kernel,
                         cudaFuncAttributeMaxDynamicSharedMemorySize, K2_SMEM);
    cudaFuncSetAttribute(attn_kernel,
                         cudaFuncAttributeMaxDynamicSharedMemorySize, K3_SMEM);

    __nv_bfloat16 *hs2, *w1, *y2, *wo2;
    float *qkv, *y;
    cudaGetSymbolAddress((void**)&hs2, g_hs2);
    cudaGetSymbolAddress((void**)&w1,  g_w1);
    cudaGetSymbolAddress((void**)&y2,  g_y2);
    cudaGetSymbolAddress((void**)&wo2, g_wo2);
    cudaGetSymbolAddress((void**)&qkv, g_qkv);
    cudaGetSymbolAddress((void**)&y,   g_y);

    split_a_kernel<<<1024, 256>>>(hs, hs2);
    split_w1_kernel<<<1536, 256>>>(Wq, Wk, Wv, w1);
    split_b_kernel<<<1024, 256>>>(Wo, wo2);

    mma_gemm_kernel<<<dim3(12, 8), 256, MMA_SMEM>>>(hs2, w1, qkv, 1536);

    chunk_kv_kernel<<<dim3(NCHUNK, NH), 256, K2_SMEM>>>();
    attn_kernel<<<dim3(NCHUNK, NH), 256, K3_SMEM>>>();

    split_a_kernel<<<1024, 256>>>(y, y2);
    mma_gemm_kernel<<<dim3(8, 8), 256, MMA_SMEM>>>(y2, wo2, out, 1024);
}

// round 8
// speedup vs baseline: 2.2629x; 1.3640x over previous
#include <cuda_runtime.h>
#include <cuda_bf16.h>
#include <cstdint>

// ---------------------------------------------------------------------------
// LinearAttention (Taylor 2nd-order feature map), b=1, l=1024, dm=1024,
// 16 heads, feature_dim=16, head_dim=64.  D = 1+16+256 = 273 features.
//
//   S:  one fused split kernel: hs->[hi|hi|lo], W1/Wo->[hi|lo|hi]  (K=3072)
//   G1: qkv = hs2 @ W1^T   (mma.sync bf16, 4-stage cp.async, frag prefetch)
//   K2: per (head,chunk): KV_c = phi(k)^T V, Kz_c = sum phi(k)  (8x4 reg tile)
//   K3: per (head,chunk): prefix state + scores + y  (4t x 8j reg tile),
//       writes split-bf16 y2 directly
//   G2: out = y2 @ Wo2^T   (128x64 tiles -> 128-CTA full wave)
// ---------------------------------------------------------------------------

#define LSEQ   1024
#define NH     16
#define CHUNK  128
#define NCHUNK 8
#define DFEAT  273
#define DP2    280                      // padded feature rows (mult of 8)
#define PHI_C1 0.5f                     // 1/d^(1/4), d=16
#define PHI_C2 0.17677669529663687f     // 1/(sqrt(2)*sqrt(d))
#define EPSV   1e-12f
#define KSPLIT 3072                     // 3 x 1024 split-bf16 K
#define NSTAGE 48                       // 3072 / 64
#define ROWB   144                      // smem row pitch (bytes) for GEMM tiles

// Scratch (static device globals; no allocation allowed)
__device__ __align__(16) float g_qkv[LSEQ * 1536];          // [l][q|k|v]
__device__ __align__(16) float g_kv[NH * NCHUNK * DP2 * 64];
__device__ __align__(16) float g_kz[NH * NCHUNK * DP2];
__device__ __align__(16) __nv_bfloat16 g_hs2[LSEQ * KSPLIT];
__device__ __align__(16) __nv_bfloat16 g_w1 [1536 * KSPLIT];
__device__ __align__(16) __nv_bfloat16 g_y2 [LSEQ * KSPLIT];
__device__ __align__(16) __nv_bfloat16 g_wo2[1024 * KSPLIT];

// ---------------- packed f32x2 helpers --------------------------------------
__device__ __forceinline__ unsigned long long pk2(float lo, float hi) {
    unsigned long long r;
    asm("mov.b64 %0, {%1, %2};" : "=l"(r)
        : "r"(__float_as_uint(lo)), "r"(__float_as_uint(hi)));
    return r;
}
__device__ __forceinline__ void ffma2(unsigned long long& d,
                                      unsigned long long a,
                                      unsigned long long b) {
    asm("fma.rn.f32x2 %0, %1, %2, %0;" : "+l"(d) : "l"(a), "l"(b));
}
__device__ __forceinline__ void upk2(unsigned long long v, float& lo, float& hi) {
    uint32_t a, b;
    asm("mov.b64 {%0, %1}, %2;" : "=r"(a), "=r"(b) : "l"(v));
    lo = __uint_as_float(a); hi = __uint_as_float(b);
}

// ---------------- PTX helpers (cp.async / ldmatrix / mma) -------------------
__device__ __forceinline__ uint32_t smem_u32(const void* p) {
    uint32_t a;
    asm("{ .reg .u64 t; cvta.to.shared.u64 t, %1; cvt.u32.u64 %0, t; }"
        : "=r"(a) : "l"(p));
    return a;
}
__device__ __forceinline__ void cp16(uint32_t saddr, const void* g) {
    asm volatile("cp.async.cg.shared.global [%0], [%1], 16;"
                 :: "r"(saddr), "l"(g) : "memory");
}
__device__ __forceinline__ void ldsm_x4(uint32_t& r0, uint32_t& r1,
                                        uint32_t& r2, uint32_t& r3,
                                        uint32_t addr) {
    asm volatile("ldmatrix.sync.aligned.m8n8.x4.shared.b16 {%0,%1,%2,%3}, [%4];"
                 : "=r"(r0), "=r"(r1), "=r"(r2), "=r"(r3) : "r"(addr));
}
__device__ __forceinline__ void mma16816(float* c, const uint32_t* a,
                                         const uint32_t* b) {
    asm volatile("mma.sync.aligned.m16n8k16.row.col.f32.bf16.bf16.f32 "
                 "{%0,%1,%2,%3}, {%4,%5,%6,%7}, {%8,%9}, {%0,%1,%2,%3};"
                 : "+f"(c[0]), "+f"(c[1]), "+f"(c[2]), "+f"(c[3])
                 : "r"(a[0]), "r"(a[1]), "r"(a[2]), "r"(a[3]),
                   "r"(b[0]), "r"(b[1]));
}

// ---------------- fused split kernel ----------------------------------------
// A layout: [hi|hi|lo], B layout: [hi|lo|hi]
__device__ __forceinline__ void split4(float4 x, __nv_bfloat162& h01,
                                       __nv_bfloat162& h23, __nv_bfloat162& l01,
                                       __nv_bfloat162& l23) {
    h01 = __floats2bfloat162_rn(x.x, x.y);
    h23 = __floats2bfloat162_rn(x.z, x.w);
    l01 = __floats2bfloat162_rn(x.x - __bfloat162float(h01.x),
                                x.y - __bfloat162float(h01.y));
    l23 = __floats2bfloat162_rn(x.z - __bfloat162float(h23.x),
                                x.w - __bfloat162float(h23.y));
}

__global__ __launch_bounds__(256) void split_all_kernel(
    const float* __restrict__ hs, const float* __restrict__ Wq,
    const float* __restrict__ Wk, const float* __restrict__ Wv,
    const float* __restrict__ Wo) {
    const int r = blockIdx.x, c = threadIdx.x * 4;
    const float* src;
    __nv_bfloat16* dst;
    bool alay;
    if (r < 1024) {
        src = hs + (size_t)r * 1024; dst = g_hs2 + (size_t)r * KSPLIT; alay = true;
    } else if (r < 2560) {
        int rr = r - 1024;
        const float* w; int wr;
        if (rr < 256)      { w = Wq; wr = rr; }
        else if (rr < 512) { w = Wk; wr = rr - 256; }
        else               { w = Wv; wr = rr - 512; }
        src = w + (size_t)wr * 1024; dst = g_w1 + (size_t)rr * KSPLIT; alay = false;
    } else {
        int rr = r - 2560;
        src = Wo + (size_t)rr * 1024; dst = g_wo2 + (size_t)rr * KSPLIT; alay = false;
    }
    float4 x = *(const float4*)&src[c];
    __nv_bfloat162 h01, h23, l01, l23;
    split4(x, h01, h23, l01, l23);
    __nv_bfloat162* d0 = (__nv_bfloat162*)&dst[c];
    __nv_bfloat162* d1 = (__nv_bfloat162*)&dst[1024 + c];
    __nv_bfloat162* d2 = (__nv_bfloat162*)&dst[2048 + c];
    d0[0] = h01; d0[1] = h23;
    if (alay) { d1[0] = h01; d1[1] = h23; d2[0] = l01; d2[1] = l23; }
    else      { d1[0] = l01; d1[1] = l23; d2[0] = h01; d2[1] = h23; }
}

// ---------------- mma.sync bf16 NT GEMM, 4-stage pipe, frag prefetch --------
template <int NTILE>
__global__ __launch_bounds__(256) void mma_gemm_kernel(
    const __nv_bfloat16* __restrict__ A, const __nv_bfloat16* __restrict__ B,
    float* __restrict__ C, int ldc) {
    constexpr int WN   = NTILE / 4;       // warp n-width (32 or 16)
    constexpr int NT8  = WN / 8;          // 8-col mma tiles per warp (4 or 2)
    constexpr int ROWS = 128 + NTILE;
    constexpr int SBYTES = ROWS * ROWB;

    extern __shared__ __align__(128) char sm[];
    const uint32_t sbase = smem_u32(sm);
    const int tid = threadIdx.x, lid = tid & 31, wid = tid >> 5;
    const int m0 = blockIdx.y * 128, n0 = blockIdx.x * NTILE;
    const int wm = wid & 1, wn = wid >> 1;

    auto load_stage = [&](int s, int buf) {
        const uint32_t base = sbase + buf * SBYTES;
#pragma unroll
        for (int i = 0; i < ROWS / 32; i++) {
            int idx = tid + i * 256;
            int row = idx >> 3, ch = idx & 7;
            const __nv_bfloat16* g =
                (row < 128)
                    ? A + (size_t)(m0 + row) * KSPLIT + s * 64 + ch * 8
                    : B + (size_t)(n0 + row - 128) * KSPLIT + s * 64 + ch * 8;
            cp16(base + row * ROWB + ch * 16, g);
        }
    };

    auto load_frags = [&](int buf, int k, uint32_t af[4][4],
                          uint32_t bfr[NT8][2]) {
        const uint32_t abase = sbase + buf * SBYTES +
            (wm * 64 + (lid & 15)) * ROWB + (lid >> 4) * 16 + k * 32;
#pragma unroll
        for (int mt = 0; mt < 4; mt++)
            ldsm_x4(af[mt][0], af[mt][1], af[mt][2], af[mt][3],
                    abase + mt * 16 * ROWB);
        const uint32_t bbase = sbase + buf * SBYTES + 128 * ROWB +
            (wn * WN + (lid & 15)) * ROWB + (lid >> 4) * 16 + k * 32;
#pragma unroll
        for (int nt2 = 0; nt2 < NT8 / 2; nt2++) {
            uint32_t r0, r1, r2, r3;
            ldsm_x4(r0, r1, r2, r3, bbase + nt2 * 16 * ROWB);
            bfr[2 * nt2][0] = r0; bfr[2 * nt2][1] = r2;
            bfr[2 * nt2 + 1][0] = r1; bfr[2 * nt2 + 1][1] = r3;
        }
    };

    float acc[4][NT8][4] = {};

    load_stage(0, 0); asm volatile("cp.async.commit_group;" ::: "memory");
    load_stage(1, 1); asm volatile("cp.async.commit_group;" ::: "memory");
    load_stage(2, 2); asm volatile("cp.async.commit_group;" ::: "memory");

    uint32_t af[2][4][4], bfr[2][NT8][2];

    for (int s = 0; s < NSTAGE; s++) {
        const int buf = s & 3;
        asm volatile("cp.async.wait_group 2;" ::: "memory");
        __syncthreads();
        load_frags(buf, 0, af[0], bfr[0]);
        if (s + 3 < NSTAGE) load_stage(s + 3, (s + 3) & 3);
        asm volatile("cp.async.commit_group;" ::: "memory");
#pragma unroll
        for (int k = 0; k < 4; k++) {
            if (k < 3) load_frags(buf, k + 1, af[(k + 1) & 1], bfr[(k + 1) & 1]);
#pragma unroll
            for (int mt = 0; mt < 4; mt++)
#pragma unroll
                for (int nt = 0; nt < NT8; nt++)
                    mma16816(acc[mt][nt], af[k & 1][mt], bfr[k & 1][nt]);
        }
    }

    const int r = lid >> 2, cq = (lid & 3) * 2;
#pragma unroll
    for (int mt = 0; mt < 4; mt++) {
        const int mrow = m0 + wm * 64 + mt * 16 + r;
#pragma unroll
        for (int nt = 0; nt < NT8; nt++) {
            const int col = n0 + wn * WN + nt * 8 + cq;
            *(float2*)&C[(size_t)mrow * ldc + col] =
                make_float2(acc[mt][nt][0], acc[mt][nt][1]);
            *(float2*)&C[(size_t)(mrow + 8) * ldc + col] =
                make_float2(acc[mt][nt][2], acc[mt][nt][3]);
        }
    }
}

// ---------------- K2: per-chunk KV / Kz sums (8d x 4j reg tiles) ------------
#define K2_SMEM ((128 * DP2 + 128 * 64 + 128 * 16) * 4)

__global__ __launch_bounds__(256) void chunk_kv_kernel() {
    extern __shared__ __align__(16) float sm2[];
    float* phik = sm2;                  // 128*280
    float* vbuf = phik + 128 * DP2;     // 128*64
    float* kbuf = vbuf + 128 * 64;      // 128*16

    const int c = blockIdx.x, h = blockIdx.y;
    const int tid = threadIdx.x;
    const int rowbase = c * CHUNK;

    for (int i = tid; i < 512; i += 256) {
        int t = i >> 2, q4 = (i & 3) * 4;
        *(float4*)&kbuf[t * 16 + q4] =
            *(const float4*)&g_qkv[(rowbase + t) * 1536 + 256 + h * 16 + q4];
    }
    for (int i = tid; i < 2048; i += 256) {
        int t = i >> 4, q4 = (i & 15) * 4;
        *(float4*)&vbuf[t * 64 + q4] =
            *(const float4*)&g_qkv[(rowbase + t) * 1536 + 512 + h * 64 + q4];
    }
    __syncthreads();

    for (int idx = tid; idx < 128 * DP2; idx += 256) {
        int t = idx / DP2;
        int D = idx - t * DP2;
        float val;
        if (D == 0)        val = 1.0f;
        else if (D <= 16)  val = kbuf[t * 16 + (D - 1)] * PHI_C1;
        else if (D < DFEAT) {
            int e = D - 17;
            val = kbuf[t * 16 + (e >> 4)] * kbuf[t * 16 + (e & 15)] * PHI_C2;
        } else val = 0.0f;
        phik[idx] = val;
    }
    __syncthreads();

    float* KVout = g_kv + (h * NCHUNK + c) * DP2 * 64;
    for (int tile = tid; tile < 35 * 16; tile += 256) {
        const int d0 = (tile >> 4) * 8;
        const int j0 = (tile & 15) * 4;
        unsigned long long acc[4][4] = {};      // [j][d-pair]
        const float* pr = &phik[d0];
        const float* vr = &vbuf[j0];
#pragma unroll 2
        for (int t = 0; t < 128; t++) {
            ulonglong2 p01 = *(const ulonglong2*)(pr + t * DP2);
            ulonglong2 p23 = *(const ulonglong2*)(pr + t * DP2 + 4);
            float4 v = *(const float4*)(vr + t * 64);
            float vv[4] = {v.x, v.y, v.z, v.w};
#pragma unroll
            for (int j = 0; j < 4; j++) {
                unsigned long long vj = pk2(vv[j], vv[j]);
                ffma2(acc[j][0], vj, p01.x);
                ffma2(acc[j][1], vj, p01.y);
                ffma2(acc[j][2], vj, p23.x);
                ffma2(acc[j][3], vj, p23.y);
            }
        }
#pragma unroll
        for (int dp = 0; dp < 4; dp++) {
            float e0[4], e1[4];
#pragma unroll
            for (int j = 0; j < 4; j++) upk2(acc[j][dp], e0[j], e1[j]);
            *(float4*)&KVout[(d0 + 2 * dp) * 64 + j0] =
                make_float4(e0[0], e0[1], e0[2], e0[3]);
            *(float4*)&KVout[(d0 + 2 * dp + 1) * 64 + j0] =
                make_float4(e1[0], e1[1], e1[2], e1[3]);
        }
    }

    float* Kzout = g_kz + (h * NCHUNK + c) * DP2;
    for (int D = tid; D < DP2; D += 256) {
        float s = 0;
#pragma unroll 4
        for (int t = 0; t < 128; t++) s += phik[t * DP2 + D];
        Kzout[D] = s;
    }
}

// ---------------- K3: attention core (4t x 8j register tiles) ---------------
#define K3_SF  (DFEAT * 64)
#define K3_SMEM ((K3_SF + DP2 + 128 * 129 + 2048 + 2048 + 8192) * 4)

__global__ __launch_bounds__(256) void attn_kernel() {
    extern __shared__ __align__(16) float sm3[];
    float* S     = sm3;                    // 273*64
    float* zbuf  = S + K3_SF;              // 280
    float* score = zbuf + DP2;             // 128*129
    float* qbuf  = score + 128 * 129;      // 2048
    float* kbuf  = qbuf + 2048;            // 2048
    float* vbuf  = kbuf + 2048;            // 8192

    const int c = blockIdx.x, h = blockIdx.y;
    const int tid = threadIdx.x;
    const int rowbase = c * CHUNK;

    for (int i = tid; i < 512; i += 256) {
        int t = i >> 2, q4 = (i & 3) * 4;
        const float* base = &g_qkv[(rowbase + t) * 1536];
        *(float4*)&qbuf[t * 16 + q4] = *(const float4*)&base[h * 16 + q4];
        *(float4*)&kbuf[t * 16 + q4] = *(const float4*)&base[256 + h * 16 + q4];
    }
    for (int i = tid; i < 2048; i += 256) {
        int t = i >> 4, q4 = (i & 15) * 4;
        *(float4*)&vbuf[t * 64 + q4] =
            *(const float4*)&g_qkv[(rowbase + t) * 1536 + 512 + h * 64 + q4];
    }

    {   // exclusive chunk-prefix state S, z
        const float* base = g_kv + (h * NCHUNK) * DP2 * 64;
        for (int i = tid; i < K3_SF / 4; i += 256) {
            float4 a = make_float4(0.f, 0.f, 0.f, 0.f);
            for (int cc = 0; cc < c; cc++) {
                float4 kv = *(const float4*)(base + cc * DP2 * 64 + i * 4);
                a.x += kv.x; a.y += kv.y; a.z += kv.z; a.w += kv.w;
            }
            *(float4*)&S[i * 4] = a;
        }
        for (int D = tid; D < DFEAT; D += 256) {
            float s = 0;
            for (int cc = 0; cc < c; cc++) s += g_kz[(h * NCHUNK + cc) * DP2 + D];
            zbuf[D] = s;
        }
    }
    __syncthreads();

    // ---- intra-chunk scores (thread = (t, half-of-s))
    {
        const int t = tid >> 1, jh = tid & 1;
        float qv[16];
#pragma unroll
        for (int i = 0; i < 16; i += 4) {
            float4 f = *(const float4*)&qbuf[t * 16 + i];
            qv[i] = f.x; qv[i + 1] = f.y; qv[i + 2] = f.z; qv[i + 3] = f.w;
        }
        unsigned long long qp[8];
#pragma unroll
        for (int i = 0; i < 8; i++) qp[i] = pk2(qv[2 * i], qv[2 * i + 1]);
        const int sbase = jh * 64;
        for (int s2 = 0; s2 < 64; s2++) {
            const int s = sbase + s2;
            unsigned long long dacc = 0ULL;
            const unsigned long long* kp = (const unsigned long long*)&kbuf[s * 16];
#pragma unroll
            for (int i = 0; i < 8; i++) ffma2(dacc, qp[i], kp[i]);
            float dlo, dhi; upk2(dacc, dlo, dhi);
            float sd = (dlo + dhi) * 0.25f;
            float sc = fmaf(0.5f * sd, sd, 1.0f + sd);
            score[t * 129 + s] = (s <= t) ? sc : 0.0f;
        }
    }
    __syncthreads();

    // ---- accumulation: thread owns t in {tg, tg+32, tg+64, tg+96}, 8 j-cols
    const int tg = tid >> 3, jg = tid & 7, j0c = jg * 8;

    float q4[4][16];
#pragma unroll
    for (int i = 0; i < 4; i++)
#pragma unroll
        for (int w = 0; w < 4; w++) {
            float4 f = *(const float4*)&qbuf[(tg + 32 * i) * 16 + w * 4];
            q4[i][w * 4 + 0] = f.x; q4[i][w * 4 + 1] = f.y;
            q4[i][w * 4 + 2] = f.z; q4[i][w * 4 + 3] = f.w;
        }

    unsigned long long acc[4][4] = {};
    float den[4] = {};

    // intra: scores are zero-masked above the diagonal, loop to max bound
    const int send = ((tg + 96) & ~15) + 16;
    const int sb0 = tg * 129, sb1 = (tg + 32) * 129,
              sb2 = (tg + 64) * 129, sb3 = (tg + 96) * 129;
    for (int s = 0; s < send; s++) {
        ulonglong2 v01 = *(const ulonglong2*)&vbuf[s * 64 + j0c];
        ulonglong2 v23 = *(const ulonglong2*)&vbuf[s * 64 + j0c + 4];
        float sc0 = score[sb0 + s], sc1 = score[sb1 + s];
        float sc2 = score[sb2 + s], sc3 = score[sb3 + s];
        den[0] += sc0; den[1] += sc1; den[2] += sc2; den[3] += sc3;
        float scv[4] = {sc0, sc1, sc2, sc3};
#pragma unroll
        for (int i = 0; i < 4; i++) {
            unsigned long long sp = pk2(scv[i], scv[i]);
            ffma2(acc[i][0], sp, v01.x);
            ffma2(acc[i][1], sp, v01.y);
            ffma2(acc[i][2], sp, v23.x);
            ffma2(acc[i][3], sp, v23.y);
        }
    }

    // inter D = 0 (phi = 1)
    {
        ulonglong2 s01 = *(const ulonglong2*)&S[j0c];
        ulonglong2 s23 = *(const ulonglong2*)&S[j0c + 4];
        const unsigned long long one2 = pk2(1.0f, 1.0f);
        const float z0 = zbuf[0];
#pragma unroll
        for (int i = 0; i < 4; i++) {
            ffma2(acc[i][0], one2, s01.x);
            ffma2(acc[i][1], one2, s01.y);
            ffma2(acc[i][2], one2, s23.x);
            ffma2(acc[i][3], one2, s23.y);
            den[i] += z0;
        }
    }
    // inter linear terms (a from smem -> loop stays rolled & small)
    for (int a = 0; a < 16; a++) {
        const float* Srow = &S[(1 + a) * 64 + j0c];
        ulonglong2 s01 = *(const ulonglong2*)Srow;
        ulonglong2 s23 = *(const ulonglong2*)(Srow + 4);
        const float z = zbuf[1 + a];
#pragma unroll
        for (int i = 0; i < 4; i++) {
            float phi = qbuf[(tg + 32 * i) * 16 + a] * PHI_C1;
            den[i] = fmaf(phi, z, den[i]);
            unsigned long long p2 = pk2(phi, phi);
            ffma2(acc[i][0], p2, s01.x);
            ffma2(acc[i][1], p2, s01.y);
            ffma2(acc[i][2], p2, s23.x);
            ffma2(acc[i][3], p2, s23.y);
        }
    }
    // inter quadratic terms: outer a from smem (rolled), inner b unrolled (regs)
    for (int a = 0; a < 16; a++) {
        float qc[4];
#pragma unroll
        for (int i = 0; i < 4; i++)
            qc[i] = qbuf[(tg + 32 * i) * 16 + a] * PHI_C2;
        const float* Sbase = &S[(17 + a * 16) * 64 + j0c];
        const float* zb = &zbuf[17 + a * 16];
#pragma unroll
        for (int b = 0; b < 16; b++) {
            ulonglong2 s01 = *(const ulonglong2*)(Sbase + b * 64);
            ulonglong2 s23 = *(const ulonglong2*)(Sbase + b * 64 + 4);
            const float z = zb[b];
#pragma unroll
            for (int i = 0; i < 4; i++) {
                float phi = qc[i] * q4[i][b];
                den[i] = fmaf(phi, z, den[i]);
                unsigned long long p2 = pk2(phi, phi);
                ffma2(acc[i][0], p2, s01.x);
                ffma2(acc[i][1], p2, s01.y);
                ffma2(acc[i][2], p2, s23.x);
                ffma2(acc[i][3], p2, s23.y);
            }
        }
    }

    // ---- y = num/(den+eps), write split-bf16 y2 directly ([hi|hi|lo])
#pragma unroll
    for (int i = 0; i < 4; i++) {
        const float rden = 1.0f / (den[i] + EPSV);
        float y[8];
#pragma unroll
        for (int g = 0; g < 4; g++) {
            float a0, a1; upk2(acc[i][g], a0, a1);
            y[2 * g] = a0 * rden; y[2 * g + 1] = a1 * rden;
        }
        union { __nv_bfloat162 b2[4]; uint4 u; } hv, lv;
#pragma unroll
        for (int g = 0; g < 4; g++) {
            __nv_bfloat162 hb = __floats2bfloat162_rn(y[2 * g], y[2 * g + 1]);
            hv.b2[g] = hb;
            lv.b2[g] = __floats2bfloat162_rn(
                y[2 * g] - __bfloat162float(hb.x),
                y[2 * g + 1] - __bfloat162float(hb.y));
        }
        const int row = rowbase + tg + 32 * i;
        __nv_bfloat16* base = g_y2 + (size_t)row * KSPLIT + h * 64 + j0c;
        *(uint4*)base          = hv.u;
        *(uint4*)(base + 1024) = hv.u;
        *(uint4*)(base + 2048) = lv.u;
    }
}

// ---------------------------------------------------------------------------
#define SM128 (4 * (256 * ROWB))      // 147456
#define SM64  (4 * (192 * ROWB))      // 110592

extern "C" void kernel_launch(void* const* d_in, const int* in_sizes, int n_in,
                              void* d_out, int out_size) {
    (void)in_sizes; (void)n_in; (void)out_size;
    const float* hs = (const float*)d_in[0];
    const float* Wq = (const float*)d_in[1];
    const float* Wk = (const float*)d_in[2];
    const float* Wv = (const float*)d_in[3];
    const float* Wo = (const float*)d_in[4];
    float* out = (float*)d_out;

    cudaFuncSetAttribute(mma_gemm_kernel<128>,
                         cudaFuncAttributeMaxDynamicSharedMemorySize, SM128);
    cudaFuncSetAttribute(mma_gemm_kernel<64>,
                         cudaFuncAttributeMaxDynamicSharedMemorySize, SM64);
    cudaFuncSetAttribute(chunk_kv_kernel,
                         cudaFuncAttributeMaxDynamicSharedMemorySize, K2_SMEM);
    cudaFuncSetAttribute(attn_kernel,
                         cudaFuncAttributeMaxDynamicSharedMemorySize, K3_SMEM);

    __nv_bfloat16 *hs2, *w1, *y2, *wo2;
    float* qkv;
    cudaGetSymbolAddress((void**)&hs2, g_hs2);
    cudaGetSymbolAddress((void**)&w1,  g_w1);
    cudaGetSymbolAddress((void**)&y2,  g_y2);
    cudaGetSymbolAddress((void**)&wo2, g_wo2);
    cudaGetSymbolAddress((void**)&qkv, g_qkv);

    split_all_kernel<<<3584, 256>>>(hs, Wq, Wk, Wv, Wo);
    mma_gemm_kernel<128><<<dim3(12, 8), 256, SM128>>>(hs2, w1, qkv, 1536);
    chunk_kv_kernel<<<dim3(NCHUNK, NH), 256, K2_SMEM>>>();
    attn_kernel<<<dim3(NCHUNK, NH), 256, K3_SMEM>>>();
    mma_gemm_kernel<64><<<dim3(16, 8), 256, SM64>>>(y2, wo2, out, 1024);
}